// round 16
// baseline (speedup 1.0000x reference)
#include <cuda_runtime.h>
#include <cuda_bf16.h>

// InterAgg (FRAUDRE inter-relation aggregation), GB300 sm_103a.
//
// out[n] = [ self | relu(self) | sum_r relu(mean_j feat[nidx_r[n,j]]) * softmax(alpha)[64:,r] ]
// (softmax rows sum to 1 => aggregated first half == relu(self) exactly)
//
// R15: R13 core + __ldcg on feature gathers. Random gathers over a 256MB
// table have ~zero L1 hit probability, so the L1 allocation __ldg performs
// on every 128B line only burns L1 fill/tag bandwidth on the gather return
// path. __ldcg keeps L2 as the dedup point (where all the real reuse is)
// and skips L1 entirely. Indices stay __ldcs, output stays __stcs (R13's
// proven pollution control), alpha stays __ldg (hot).

#define NB 8192
#define DEG 32
#define ED 64

__device__ __forceinline__ void softmax3(float& a, float& b, float& c) {
    float m = fmaxf(a, fmaxf(b, c));
    float e0 = __expf(a - m);
    float e1 = __expf(b - m);
    float e2 = __expf(c - m);
    float inv = __frcp_rn(e0 + e1 + e2);
    a = e0 * inv; b = e1 * inv; c = e2 * inv;
}

__global__ __launch_bounds__(256, 8)
void interagg_kernel(const float2* __restrict__ feat2,   // features as float2[NUM_NODES*32]
                     const float*  __restrict__ alpha,   // (128, 3)
                     const int*    __restrict__ nodes,   // (NB,)
                     const int*    __restrict__ n1,      // (NB, DEG)
                     const int*    __restrict__ n2,
                     const int*    __restrict__ n3,
                     float*        __restrict__ out)     // (NB, 192)
{
    const int w    = (blockIdx.x * blockDim.x + threadIdx.x) >> 5;
    const int lane = threadIdx.x & 31;
    if (w >= NB) return;

    // --- index loads (coalesced, streaming: read-once per iteration) ---
    const int node = __ldcs(&nodes[w]);
    const int base = w * DEG + lane;
    const int i1 = __ldcs(&n1[base]);
    const int i2 = __ldcs(&n2[base]);
    const int i3 = __ldcs(&n3[base]);

    // --- self row gather: lane l reads float2 at dims {2l,2l+1} ---
    const float2 s = __ldcg(&feat2[node * 32 + lane]);

    // --- neighbor gathers: 96 coalesced 256B row reads per warp, L2-only ---
    float2 a1 = make_float2(0.f, 0.f);
    float2 a2 = make_float2(0.f, 0.f);
    float2 a3 = make_float2(0.f, 0.f);

#pragma unroll
    for (int j = 0; j < DEG; j++) {
        const int x1 = __shfl_sync(0xffffffffu, i1, j);
        const int x2 = __shfl_sync(0xffffffffu, i2, j);
        const int x3 = __shfl_sync(0xffffffffu, i3, j);
        const float2 v1 = __ldcg(&feat2[x1 * 32 + lane]);
        const float2 v2 = __ldcg(&feat2[x2 * 32 + lane]);
        const float2 v3 = __ldcg(&feat2[x3 * 32 + lane]);
        a1.x += v1.x; a1.y += v1.y;
        a2.x += v2.x; a2.y += v2.y;
        a3.x += v3.x; a3.y += v3.y;
    }

    // --- per-dim softmax weights, agg half only (alpha rows 64+2l, 65+2l) ---
    const int r0 = (ED + 2 * lane) * 3;
    float w00 = __ldg(&alpha[r0 + 0]), w01 = __ldg(&alpha[r0 + 1]), w02 = __ldg(&alpha[r0 + 2]);
    float w10 = __ldg(&alpha[r0 + 3]), w11 = __ldg(&alpha[r0 + 4]), w12 = __ldg(&alpha[r0 + 5]);
    softmax3(w00, w01, w02);
    softmax3(w10, w11, w12);

    const float inv = 1.0f / (float)DEG;
    const float g1x = fmaxf(a1.x * inv, 0.f), g1y = fmaxf(a1.y * inv, 0.f);
    const float g2x = fmaxf(a2.x * inv, 0.f), g2y = fmaxf(a2.y * inv, 0.f);
    const float g3x = fmaxf(a3.x * inv, 0.f), g3y = fmaxf(a3.y * inv, 0.f);

    const float ox = g1x * w00 + g2x * w01 + g3x * w02;
    const float oy = g1y * w10 + g2y * w11 + g3y * w12;

    // --- write 192 floats: [self | relu(self) | weighted agg], streaming ---
    float* ob = out + (size_t)w * 192;
    __stcs(&reinterpret_cast<float2*>(ob)[lane], s);
    __stcs(&reinterpret_cast<float2*>(ob + 64)[lane],
           make_float2(fmaxf(s.x, 0.f), fmaxf(s.y, 0.f)));
    __stcs(&reinterpret_cast<float2*>(ob + 128)[lane], make_float2(ox, oy));
}

extern "C" void kernel_launch(void* const* d_in, const int* in_sizes, int n_in,
                              void* d_out, int out_size) {
    const float2* feat2 = (const float2*)d_in[0];
    const float*  alpha = (const float*)d_in[1];
    const int*    nodes = (const int*)d_in[2];
    const int*    n1    = (const int*)d_in[3];
    const int*    n2    = (const int*)d_in[4];
    const int*    n3    = (const int*)d_in[5];
    float*        out   = (float*)d_out;

    const int threads = 256;                                // 8 warps = 8 nodes / block
    const int blocks  = (NB * 32 + threads - 1) / threads;  // 1024
    interagg_kernel<<<blocks, threads>>>(feat2, alpha, nodes, n1, n2, n3, out);
}

// round 17
// speedup vs baseline: 1.0077x; 1.0077x over previous
#include <cuda_runtime.h>
#include <cuda_bf16.h>

// InterAgg (FRAUDRE inter-relation aggregation), GB300 sm_103a.
//
// out[n] = [ self | relu(self) | sum_r relu(mean_j feat[nidx_r[n,j]]) * softmax(alpha)[64:,r] ]
// (softmax rows sum to 1 => aggregated first half == relu(self) exactly)
//
// TERMINAL (R13 config, best measured 29.15us):
//  - one warp per batch node; lane l owns float2 dims {2l,2l+1} so every
//    gathered 256B feature row is one fully-coalesced warp transaction
//  - feature gathers via __ldg (L2 is the dedup point for duplicate rows)
//  - index reads via __ldcs, output writes via __stcs (single-touch streams
//    kept out of L2 so feature lines own the cache; R13's measured -1.6us)
//  - softmax-sums-to-1 identity removes the first-half weighting entirely
// Measured: 159MB DRAM traffic vs ~150MB unique-row floor; 5.4TB/s achieved
// on random 256B rows (the HBM3e row-activation ceiling for this pattern).
// All scheduling/engine/hint levers falsified in R1-R15.

#define NB 8192
#define DEG 32
#define ED 64

__device__ __forceinline__ void softmax3(float& a, float& b, float& c) {
    float m = fmaxf(a, fmaxf(b, c));
    float e0 = __expf(a - m);
    float e1 = __expf(b - m);
    float e2 = __expf(c - m);
    float inv = __frcp_rn(e0 + e1 + e2);
    a = e0 * inv; b = e1 * inv; c = e2 * inv;
}

__global__ __launch_bounds__(256, 8)
void interagg_kernel(const float2* __restrict__ feat2,   // features as float2[NUM_NODES*32]
                     const float*  __restrict__ alpha,   // (128, 3)
                     const int*    __restrict__ nodes,   // (NB,)
                     const int*    __restrict__ n1,      // (NB, DEG)
                     const int*    __restrict__ n2,
                     const int*    __restrict__ n3,
                     float*        __restrict__ out)     // (NB, 192)
{
    const int w    = (blockIdx.x * blockDim.x + threadIdx.x) >> 5;
    const int lane = threadIdx.x & 31;
    if (w >= NB) return;

    // --- index loads (coalesced, streaming: read-once per iteration) ---
    const int node = __ldcs(&nodes[w]);
    const int base = w * DEG + lane;
    const int i1 = __ldcs(&n1[base]);
    const int i2 = __ldcs(&n2[base]);
    const int i3 = __ldcs(&n3[base]);

    // --- self row gather: lane l reads float2 at dims {2l,2l+1} ---
    const float2 s = __ldg(&feat2[node * 32 + lane]);

    // --- neighbor gathers: 96 coalesced 256B row reads per warp ---
    float2 a1 = make_float2(0.f, 0.f);
    float2 a2 = make_float2(0.f, 0.f);
    float2 a3 = make_float2(0.f, 0.f);

#pragma unroll
    for (int j = 0; j < DEG; j++) {
        const int x1 = __shfl_sync(0xffffffffu, i1, j);
        const int x2 = __shfl_sync(0xffffffffu, i2, j);
        const int x3 = __shfl_sync(0xffffffffu, i3, j);
        const float2 v1 = __ldg(&feat2[x1 * 32 + lane]);
        const float2 v2 = __ldg(&feat2[x2 * 32 + lane]);
        const float2 v3 = __ldg(&feat2[x3 * 32 + lane]);
        a1.x += v1.x; a1.y += v1.y;
        a2.x += v2.x; a2.y += v2.y;
        a3.x += v3.x; a3.y += v3.y;
    }

    // --- per-dim softmax weights, agg half only (alpha rows 64+2l, 65+2l) ---
    const int r0 = (ED + 2 * lane) * 3;
    float w00 = __ldg(&alpha[r0 + 0]), w01 = __ldg(&alpha[r0 + 1]), w02 = __ldg(&alpha[r0 + 2]);
    float w10 = __ldg(&alpha[r0 + 3]), w11 = __ldg(&alpha[r0 + 4]), w12 = __ldg(&alpha[r0 + 5]);
    softmax3(w00, w01, w02);
    softmax3(w10, w11, w12);

    const float inv = 1.0f / (float)DEG;
    const float g1x = fmaxf(a1.x * inv, 0.f), g1y = fmaxf(a1.y * inv, 0.f);
    const float g2x = fmaxf(a2.x * inv, 0.f), g2y = fmaxf(a2.y * inv, 0.f);
    const float g3x = fmaxf(a3.x * inv, 0.f), g3y = fmaxf(a3.y * inv, 0.f);

    const float ox = g1x * w00 + g2x * w01 + g3x * w02;
    const float oy = g1y * w10 + g2y * w11 + g3y * w12;

    // --- write 192 floats: [self | relu(self) | weighted agg], streaming ---
    float* ob = out + (size_t)w * 192;
    __stcs(&reinterpret_cast<float2*>(ob)[lane], s);
    __stcs(&reinterpret_cast<float2*>(ob + 64)[lane],
           make_float2(fmaxf(s.x, 0.f), fmaxf(s.y, 0.f)));
    __stcs(&reinterpret_cast<float2*>(ob + 128)[lane], make_float2(ox, oy));
}

extern "C" void kernel_launch(void* const* d_in, const int* in_sizes, int n_in,
                              void* d_out, int out_size) {
    const float2* feat2 = (const float2*)d_in[0];
    const float*  alpha = (const float*)d_in[1];
    const int*    nodes = (const int*)d_in[2];
    const int*    n1    = (const int*)d_in[3];
    const int*    n2    = (const int*)d_in[4];
    const int*    n3    = (const int*)d_in[5];
    float*        out   = (float*)d_out;

    const int threads = 256;                                // 8 warps = 8 nodes / block
    const int blocks  = (NB * 32 + threads - 1) / threads;  // 1024
    interagg_kernel<<<blocks, threads>>>(feat2, alpha, nodes, n1, n2, n3, out);
}